// round 7
// baseline (speedup 1.0000x reference)
#include <cuda_runtime.h>
#include <cuda_bf16.h>
#include <cstdint>
#include <math.h>

// Problem constants
#define N_TOK 4096
#define DIN   512
#define HDIM  2048
#define NEXP  8
#define NSLOT 8192
#define SA 40    // A smem stride (bf16): 32 + 8 pad
#define SB 136   // B smem stride (bf16): 128 + 8 pad

// ---------------- device scratch (~80 MB, same footprint class as the passing R3 kernel) ----------------
__device__ int   g_counts[NEXP];
__device__ int   g_list[NEXP * NSLOT];
__device__ int   g_is64;
__device__ float g_zero[HDIM];                 // stays all-zero
__device__ float g_h[(size_t)NSLOT * HDIM];    // 64 MB hidden (fp32)
__device__ float g_y[(size_t)NSLOT * DIN];     // 16 MB per-slot outputs

// ---------------- PTX macros: scalar operands only ----------------
__device__ __forceinline__ uint32_t smem_u32(const void* p) {
    uint32_t a;
    asm("{ .reg .u64 t; cvta.to.shared.u64 t, %1; cvt.u32.u64 %0, t; }"
        : "=r"(a) : "l"(p));
    return a;
}
#define LDM_X4(r0, r1, r2, r3, a) \
    asm volatile("ldmatrix.sync.aligned.m8n8.x4.shared.b16 {%0,%1,%2,%3}, [%4];" \
                 : "=r"(r0), "=r"(r1), "=r"(r2), "=r"(r3) : "r"(a))
#define LDM_X2T(r0, r1, a) \
    asm volatile("ldmatrix.sync.aligned.m8n8.x2.trans.shared.b16 {%0,%1}, [%2];" \
                 : "=r"(r0), "=r"(r1) : "r"(a))
#define MMA16816(c0, c1, c2, c3, a0, a1, a2, a3, b0, b1) \
    asm volatile("mma.sync.aligned.m16n8k16.row.col.f32.bf16.bf16.f32 " \
                 "{%0,%1,%2,%3}, {%4,%5,%6,%7}, {%8,%9}, {%0,%1,%2,%3};" \
                 : "+f"(c0), "+f"(c1), "+f"(c2), "+f"(c3) \
                 : "r"(a0), "r"(a1), "r"(a2), "r"(a3), "r"(b0), "r"(b1))
// 3-term accumulate: hi*hi + lo*hi + hi*lo
#define MMA3(C, AH, AL, BH, BL) do { \
    MMA16816(C.x, C.y, C.z, C.w, AH.x, AH.y, AH.z, AH.w, BH.x, BH.y); \
    MMA16816(C.x, C.y, C.z, C.w, AL.x, AL.y, AL.z, AL.w, BH.x, BH.y); \
    MMA16816(C.x, C.y, C.z, C.w, AH.x, AH.y, AH.z, AH.w, BL.x, BL.y); \
} while (0)

// ---------------- dispatch ----------------
__global__ void k_reset(const int* idx32) {
    int t = threadIdx.x;
    if (t < NEXP) g_counts[t] = 0;
    if (t == 0) {
        int allz = 1;
        #pragma unroll
        for (int i = 1; i < 32; i += 2)
            if (idx32[i] != 0) allz = 0;
        g_is64 = allz;
    }
}
__global__ void k_build(const void* idxp) {
    int s = blockIdx.x * blockDim.x + threadIdx.x;
    if (s >= NSLOT) return;
    int e = g_is64 ? (int)((const long long*)idxp)[s] : ((const int*)idxp)[s];
    int pos = atomicAdd(&g_counts[e], 1);
    g_list[e * NSLOT + pos] = s;
}

__device__ __forceinline__ float gelu_tanh(float v) {
    float u = 0.7978845608028654f * (v + 0.044715f * v * v * v);
    return 0.5f * v * (1.0f + tanhf(u));
}

// ---------------- fused-convert tensor-core grouped GEMM ----------------
// MODE 1: h = gelu(gather(x) @ W1[e] + b1[e])   K=512,  Ntot=2048, A row = slot>>1
// MODE 2: y = gather(h) @ W2[e] + b2[e]         K=2048, Ntot=512,  A row = slot
// W layout is natural [E][K][Ntot]; B tiles loaded [k][n] and fed via ldmatrix.trans.
template <int MODE>
__global__ __launch_bounds__(256, 1)
void k_mma(const float* __restrict__ Asrc_in, const float* __restrict__ W,
           const float* __restrict__ bias) {
    __shared__ __align__(16) __nv_bfloat16 sAh[128 * SA];
    __shared__ __align__(16) __nv_bfloat16 sAl[128 * SA];
    __shared__ __align__(16) __nv_bfloat16 sBh[32 * SB];
    __shared__ __align__(16) __nv_bfloat16 sBl[32 * SB];
    __shared__ const float* s_aptr[128];
    __shared__ int s_slot[128];

    const int e   = blockIdx.z;
    const int cnt = g_counts[e];
    const int m0  = blockIdx.y * 128;
    if (m0 >= cnt) return;
    const int n0  = blockIdx.x * 128;
    const int tid = threadIdx.x;
    const int lane = tid & 31, w = tid >> 5;
    const int wm = w & 1, wn = w >> 1;          // 2x4 warp grid, warp tile 64x32

    constexpr int K    = (MODE == 1) ? DIN : HDIM;
    constexpr int Ntot = (MODE == 1) ? HDIM : DIN;
    const float* Asrc = (MODE == 1) ? Asrc_in : (const float*)g_h;
    const float* Bsrc = W + (size_t)e * K * Ntot;

    if (tid < 128) {
        int m = m0 + tid;
        if (m < cnt) {
            int s = g_list[e * NSLOT + m];
            s_slot[tid] = s;
            int r = (MODE == 1) ? (s >> 1) : s;
            s_aptr[tid] = Asrc + (size_t)r * K;
        } else {
            s_slot[tid] = -1;
            s_aptr[tid] = g_zero;
        }
    }
    __syncthreads();

    const uint32_t sAh0 = smem_u32(sAh), sAl0 = smem_u32(sAl);
    const uint32_t sBh0 = smem_u32(sBh), sBl0 = smem_u32(sBl);

    float4 c00 = make_float4(0.f, 0.f, 0.f, 0.f), c01 = c00, c02 = c00, c03 = c00;
    float4 c10 = c00, c11 = c00, c12 = c00, c13 = c00;
    float4 c20 = c00, c21 = c00, c22 = c00, c23 = c00;
    float4 c30 = c00, c31 = c00, c32 = c00, c33 = c00;

    constexpr int nch = K / 32;
    for (int ch = 0; ch < nch; ch++) {
        const int k0 = ch * 32;
        // ---- fill A (128x32 fp32 -> bf16 hi/lo) ----
        #pragma unroll
        for (int u = 0; u < 4; u++) {
            int unit = tid + u * 256;            // 1024 float4 units
            int r = unit >> 3, p = unit & 7;
            float4 v = *(const float4*)(s_aptr[r] + k0 + p * 4);
            __nv_bfloat16 h0 = __float2bfloat16(v.x);
            __nv_bfloat16 h1 = __float2bfloat16(v.y);
            __nv_bfloat16 h2 = __float2bfloat16(v.z);
            __nv_bfloat16 h3 = __float2bfloat16(v.w);
            int o = r * SA + p * 4;
            *(__nv_bfloat162*)(sAh + o)     = __nv_bfloat162{h0, h1};
            *(__nv_bfloat162*)(sAh + o + 2) = __nv_bfloat162{h2, h3};
            *(__nv_bfloat162*)(sAl + o) = __nv_bfloat162{
                __float2bfloat16(v.x - __bfloat162float(h0)),
                __float2bfloat16(v.y - __bfloat162float(h1))};
            *(__nv_bfloat162*)(sAl + o + 2) = __nv_bfloat162{
                __float2bfloat16(v.z - __bfloat162float(h2)),
                __float2bfloat16(v.w - __bfloat162float(h3))};
        }
        // ---- fill B (32x128 fp32, natural [k][n] layout, coalesced in n) ----
        #pragma unroll
        for (int u = 0; u < 4; u++) {
            int unit = tid + u * 256;            // 1024 float4 units
            int r = unit >> 5, p = unit & 31;
            float4 v = *(const float4*)(Bsrc + (size_t)(k0 + r) * Ntot + n0 + p * 4);
            __nv_bfloat16 h0 = __float2bfloat16(v.x);
            __nv_bfloat16 h1 = __float2bfloat16(v.y);
            __nv_bfloat16 h2 = __float2bfloat16(v.z);
            __nv_bfloat16 h3 = __float2bfloat16(v.w);
            int o = r * SB + p * 4;
            *(__nv_bfloat162*)(sBh + o)     = __nv_bfloat162{h0, h1};
            *(__nv_bfloat162*)(sBh + o + 2) = __nv_bfloat162{h2, h3};
            *(__nv_bfloat162*)(sBl + o) = __nv_bfloat162{
                __float2bfloat16(v.x - __bfloat162float(h0)),
                __float2bfloat16(v.y - __bfloat162float(h1))};
            *(__nv_bfloat162*)(sBl + o + 2) = __nv_bfloat162{
                __float2bfloat16(v.z - __bfloat162float(h2)),
                __float2bfloat16(v.w - __bfloat162float(h3))};
        }
        __syncthreads();

        // ---- compute: 2 k16 steps x 16 (i,j) tiles x 3 terms ----
        #pragma unroll
        for (int kk = 0; kk < 32; kk += 16) {
            const uint32_t aoff = ((wm * 64 + (lane & 15)) * SA + kk + (lane >> 4) * 8) * 2;
            uint4 Ah0, Ah1, Ah2, Ah3, Al0, Al1, Al2, Al3;
            LDM_X4(Ah0.x, Ah0.y, Ah0.z, Ah0.w, sAh0 + aoff);
            LDM_X4(Ah1.x, Ah1.y, Ah1.z, Ah1.w, sAh0 + aoff + 16 * SA * 2);
            LDM_X4(Ah2.x, Ah2.y, Ah2.z, Ah2.w, sAh0 + aoff + 32 * SA * 2);
            LDM_X4(Ah3.x, Ah3.y, Ah3.z, Ah3.w, sAh0 + aoff + 48 * SA * 2);
            LDM_X4(Al0.x, Al0.y, Al0.z, Al0.w, sAl0 + aoff);
            LDM_X4(Al1.x, Al1.y, Al1.z, Al1.w, sAl0 + aoff + 16 * SA * 2);
            LDM_X4(Al2.x, Al2.y, Al2.z, Al2.w, sAl0 + aoff + 32 * SA * 2);
            LDM_X4(Al3.x, Al3.y, Al3.z, Al3.w, sAl0 + aoff + 48 * SA * 2);

            const uint32_t boff = ((kk + (lane & 15)) * SB + wn * 32) * 2;
            uint2 Bh0, Bh1, Bh2, Bh3, Bl0, Bl1, Bl2, Bl3;
            LDM_X2T(Bh0.x, Bh0.y, sBh0 + boff);
            LDM_X2T(Bh1.x, Bh1.y, sBh0 + boff + 16);
            LDM_X2T(Bh2.x, Bh2.y, sBh0 + boff + 32);
            LDM_X2T(Bh3.x, Bh3.y, sBh0 + boff + 48);
            LDM_X2T(Bl0.x, Bl0.y, sBl0 + boff);
            LDM_X2T(Bl1.x, Bl1.y, sBl0 + boff + 16);
            LDM_X2T(Bl2.x, Bl2.y, sBl0 + boff + 32);
            LDM_X2T(Bl3.x, Bl3.y, sBl0 + boff + 48);

            MMA3(c00, Ah0, Al0, Bh0, Bl0); MMA3(c01, Ah0, Al0, Bh1, Bl1);
            MMA3(c02, Ah0, Al0, Bh2, Bl2); MMA3(c03, Ah0, Al0, Bh3, Bl3);
            MMA3(c10, Ah1, Al1, Bh0, Bl0); MMA3(c11, Ah1, Al1, Bh1, Bl1);
            MMA3(c12, Ah1, Al1, Bh2, Bl2); MMA3(c13, Ah1, Al1, Bh3, Bl3);
            MMA3(c20, Ah2, Al2, Bh0, Bl0); MMA3(c21, Ah2, Al2, Bh1, Bl1);
            MMA3(c22, Ah2, Al2, Bh2, Bl2); MMA3(c23, Ah2, Al2, Bh3, Bl3);
            MMA3(c30, Ah3, Al3, Bh0, Bl0); MMA3(c31, Ah3, Al3, Bh1, Bl1);
            MMA3(c32, Ah3, Al3, Bh2, Bl2); MMA3(c33, Ah3, Al3, Bh3, Bl3);
        }
        __syncthreads();
    }

    // ---- epilogue ----
    const float* bptr = bias + (size_t)e * Ntot + n0;
#define EPI(C, I, J) do { \
    int r0_ = wm * 64 + (I) * 16 + (lane >> 2); \
    int s0_ = s_slot[r0_], s1_ = s_slot[r0_ + 8]; \
    int col_ = wn * 32 + (J) * 8 + (lane & 3) * 2; \
    float b0_ = bptr[col_], b1_ = bptr[col_ + 1]; \
    if (MODE == 1) { \
        if (s0_ >= 0) { \
            float2 o_ = make_float2(gelu_tanh(C.x + b0_), gelu_tanh(C.y + b1_)); \
            *(float2*)(g_h + (size_t)s0_ * HDIM + n0 + col_) = o_; \
        } \
        if (s1_ >= 0) { \
            float2 o_ = make_float2(gelu_tanh(C.z + b0_), gelu_tanh(C.w + b1_)); \
            *(float2*)(g_h + (size_t)s1_ * HDIM + n0 + col_) = o_; \
        } \
    } else { \
        if (s0_ >= 0) \
            *(float2*)(g_y + (size_t)s0_ * DIN + n0 + col_) = make_float2(C.x + b0_, C.y + b1_); \
        if (s1_ >= 0) \
            *(float2*)(g_y + (size_t)s1_ * DIN + n0 + col_) = make_float2(C.z + b0_, C.w + b1_); \
    } \
} while (0)
    EPI(c00, 0, 0); EPI(c01, 0, 1); EPI(c02, 0, 2); EPI(c03, 0, 3);
    EPI(c10, 1, 0); EPI(c11, 1, 1); EPI(c12, 1, 2); EPI(c13, 1, 3);
    EPI(c20, 2, 0); EPI(c21, 2, 1); EPI(c22, 2, 2); EPI(c23, 2, 3);
    EPI(c30, 3, 0); EPI(c31, 3, 1); EPI(c32, 3, 2); EPI(c33, 3, 3);
#undef EPI
}

// ---------------- combine + loss tail ----------------
__global__ void k_comb(const float* __restrict__ p, float* __restrict__ out) {
    int i = blockIdx.x * blockDim.x + threadIdx.x;
    if (i >= N_TOK * DIN / 4) return;
    int t = i / (DIN / 4);
    int d4 = i % (DIN / 4);
    float p0 = p[t * 2], p1 = p[t * 2 + 1];
    float4 y0 = *(const float4*)(g_y + (size_t)(2 * t) * DIN + d4 * 4);
    float4 y1 = *(const float4*)(g_y + (size_t)(2 * t + 1) * DIN + d4 * 4);
    float4 o;
    o.x = p0 * y0.x + p1 * y1.x;
    o.y = p0 * y0.y + p1 * y1.y;
    o.z = p0 * y0.z + p1 * y1.z;
    o.w = p0 * y0.w + p1 * y1.w;
    *(float4*)(out + (size_t)i * 4) = o;
}
__global__ void k_tail(float* __restrict__ out, int begin, int total) {
    int i = begin + blockIdx.x * blockDim.x + threadIdx.x;
    if (i < total) out[i] = 0.0f;
}

extern "C" void kernel_launch(void* const* d_in, const int* in_sizes, int n_in,
                              void* d_out, int out_size) {
    const float* x    = (const float*)d_in[0];
    const float* prob = (const float*)d_in[1];
    const void*  idx  = d_in[2];
    const float* W1   = (const float*)d_in[3];
    const float* b1   = (const float*)d_in[4];
    const float* W2   = (const float*)d_in[5];
    const float* b2   = (const float*)d_in[6];
    float* out = (float*)d_out;

    k_reset<<<1, 32>>>((const int*)idx);
    k_build<<<NSLOT / 256, 256>>>(idx);

    k_mma<1><<<dim3(HDIM / 128, NSLOT / 128, NEXP), 256>>>(x, W1, b1);
    k_mma<2><<<dim3(DIN / 128, NSLOT / 128, NEXP), 256>>>(nullptr, W2, b2);

    k_comb<<<(N_TOK * DIN / 4 + 255) / 256, 256>>>(prob, out);
    int tail = out_size - N_TOK * DIN;
    if (tail > 0)
        k_tail<<<(tail + 255) / 256, 256>>>(out, N_TOK * DIN, out_size);
    (void)in_sizes; (void)n_in;
}

// round 9
// speedup vs baseline: 2.0551x; 2.0551x over previous
#include <cuda_runtime.h>
#include <cuda_bf16.h>
#include <cstdint>
#include <math.h>

// Problem constants
#define N_TOK 4096
#define DIN   512
#define HDIM  2048
#define NEXP  8
#define NSLOT 8192
#define SA 40    // A smem stride (bf16): 32 + 8 pad
#define SB 136   // B smem stride (bf16): 128 + 8 pad

// ---------------- device scratch (~80 MB, identical to the passing R7 kernel) ----------------
__device__ int   g_counts[NEXP];
__device__ int   g_list[NEXP * NSLOT];
__device__ int   g_is64;
__device__ float g_zero[HDIM];                 // stays all-zero
__device__ float g_h[(size_t)NSLOT * HDIM];    // 64 MB hidden (fp32)
__device__ float g_y[(size_t)NSLOT * DIN];     // 16 MB per-slot outputs

// ---------------- PTX macros: scalar operands only ----------------
__device__ __forceinline__ uint32_t smem_u32(const void* p) {
    uint32_t a;
    asm("{ .reg .u64 t; cvta.to.shared.u64 t, %1; cvt.u32.u64 %0, t; }"
        : "=r"(a) : "l"(p));
    return a;
}
#define LDM_X4(r0, r1, r2, r3, a) \
    asm volatile("ldmatrix.sync.aligned.m8n8.x4.shared.b16 {%0,%1,%2,%3}, [%4];" \
                 : "=r"(r0), "=r"(r1), "=r"(r2), "=r"(r3) : "r"(a))
#define LDM_X2T(r0, r1, a) \
    asm volatile("ldmatrix.sync.aligned.m8n8.x2.trans.shared.b16 {%0,%1}, [%2];" \
                 : "=r"(r0), "=r"(r1) : "r"(a))
#define MMA16816(c0, c1, c2, c3, a0, a1, a2, a3, b0, b1) \
    asm volatile("mma.sync.aligned.m16n8k16.row.col.f32.bf16.bf16.f32 " \
                 "{%0,%1,%2,%3}, {%4,%5,%6,%7}, {%8,%9}, {%0,%1,%2,%3};" \
                 : "+f"(c0), "+f"(c1), "+f"(c2), "+f"(c3) \
                 : "r"(a0), "r"(a1), "r"(a2), "r"(a3), "r"(b0), "r"(b1))
// 3-term accumulate: hi*hi + lo*hi + hi*lo
#define MMA3(C, AH, AL, BH, BL) do { \
    MMA16816(C.x, C.y, C.z, C.w, AH.x, AH.y, AH.z, AH.w, BH.x, BH.y); \
    MMA16816(C.x, C.y, C.z, C.w, AL.x, AL.y, AL.z, AL.w, BH.x, BH.y); \
    MMA16816(C.x, C.y, C.z, C.w, AH.x, AH.y, AH.z, AH.w, BL.x, BL.y); \
} while (0)

// ---------------- dispatch ----------------
__global__ void k_reset(const int* idx32) {
    int t = threadIdx.x;
    if (t < NEXP) g_counts[t] = 0;
    if (t == 0) {
        int allz = 1;
        #pragma unroll
        for (int i = 1; i < 32; i += 2)
            if (idx32[i] != 0) allz = 0;
        g_is64 = allz;
    }
}
__global__ void k_build(const void* idxp) {
    int s = blockIdx.x * blockDim.x + threadIdx.x;
    if (s >= NSLOT) return;
    int e = g_is64 ? (int)((const long long*)idxp)[s] : ((const int*)idxp)[s];
    int pos = atomicAdd(&g_counts[e], 1);
    g_list[e * NSLOT + pos] = s;
}

__device__ __forceinline__ float gelu_tanh(float v) {
    float u = 0.7978845608028654f * (v + 0.044715f * v * v * v);
    return 0.5f * v * (1.0f + tanhf(u));
}

// ---------------- fused-convert tensor-core grouped GEMM, LDG-prefetch pipelined ----------------
// MODE 1: h = gelu(gather(x) @ W1[e] + b1[e])   K=512,  Ntot=2048, A row = slot>>1
// MODE 2: y = gather(h) @ W2[e] + b2[e]         K=2048, Ntot=512,  A row = slot
// W layout natural [E][K][Ntot]; B tiles [k][n] fed via ldmatrix.trans.
// Per chunk: store prefetched regs -> smem (with bf16 hi/lo convert), sync,
// issue LDGs for the NEXT chunk into named registers, then run the MMA burst
// (loads in flight behind it), sync.
template <int MODE>
__global__ __launch_bounds__(256, 1)
void k_mma(const float* __restrict__ Asrc_in, const float* __restrict__ W,
           const float* __restrict__ bias) {
    __shared__ __align__(16) __nv_bfloat16 sAh[128 * SA];
    __shared__ __align__(16) __nv_bfloat16 sAl[128 * SA];
    __shared__ __align__(16) __nv_bfloat16 sBh[32 * SB];
    __shared__ __align__(16) __nv_bfloat16 sBl[32 * SB];
    __shared__ const float* s_aptr[128];
    __shared__ int s_slot[128];

    const int e   = blockIdx.z;
    const int cnt = g_counts[e];
    const int m0  = blockIdx.y * 128;
    if (m0 >= cnt) return;
    const int n0  = blockIdx.x * 128;
    const int tid = threadIdx.x;
    const int lane = tid & 31, w = tid >> 5;
    const int wm = w & 1, wn = w >> 1;          // 2x4 warp grid, warp tile 64x32

    constexpr int K    = (MODE == 1) ? DIN : HDIM;
    constexpr int Ntot = (MODE == 1) ? HDIM : DIN;
    const float* Asrc = (MODE == 1) ? Asrc_in : (const float*)g_h;
    const float* Bsrc = W + (size_t)e * K * Ntot;

    if (tid < 128) {
        int m = m0 + tid;
        if (m < cnt) {
            int s = g_list[e * NSLOT + m];
            s_slot[tid] = s;
            int r = (MODE == 1) ? (s >> 1) : s;
            s_aptr[tid] = Asrc + (size_t)r * K;
        } else {
            s_slot[tid] = -1;
            s_aptr[tid] = g_zero;
        }
    }
    __syncthreads();

    const uint32_t sAh0 = smem_u32(sAh), sAl0 = smem_u32(sAl);
    const uint32_t sBh0 = smem_u32(sBh), sBl0 = smem_u32(sBl);

    float4 c00 = make_float4(0.f, 0.f, 0.f, 0.f), c01 = c00, c02 = c00, c03 = c00;
    float4 c10 = c00, c11 = c00, c12 = c00, c13 = c00;
    float4 c20 = c00, c21 = c00, c22 = c00, c23 = c00;
    float4 c30 = c00, c31 = c00, c32 = c00, c33 = c00;

    // prefetch registers (named scalars; chunk's 128x32 A + 32x128 B split over 256 threads)
    float4 pa0, pa1, pa2, pa3, pb0, pb1, pb2, pb3;

#define LDG_A(V, U, K0) do { \
    int unit_ = tid + (U) * 256; \
    int r_ = unit_ >> 3, p_ = unit_ & 7; \
    V = *(const float4*)(s_aptr[r_] + (K0) + p_ * 4); \
} while (0)
#define LDG_B(V, U, K0) do { \
    int unit_ = tid + (U) * 256; \
    int r_ = unit_ >> 5, p_ = unit_ & 31; \
    V = *(const float4*)(Bsrc + (size_t)((K0) + r_) * Ntot + n0 + p_ * 4); \
} while (0)
#define PREF(K0) do { \
    LDG_A(pa0, 0, K0); LDG_A(pa1, 1, K0); LDG_A(pa2, 2, K0); LDG_A(pa3, 3, K0); \
    LDG_B(pb0, 0, K0); LDG_B(pb1, 1, K0); LDG_B(pb2, 2, K0); LDG_B(pb3, 3, K0); \
} while (0)
#define ST_A(V, U) do { \
    int unit_ = tid + (U) * 256; \
    int r_ = unit_ >> 3, p_ = unit_ & 7; \
    __nv_bfloat16 h0_ = __float2bfloat16(V.x), h1_ = __float2bfloat16(V.y); \
    __nv_bfloat16 h2_ = __float2bfloat16(V.z), h3_ = __float2bfloat16(V.w); \
    int o_ = r_ * SA + p_ * 4; \
    *(__nv_bfloat162*)(sAh + o_)     = __nv_bfloat162{h0_, h1_}; \
    *(__nv_bfloat162*)(sAh + o_ + 2) = __nv_bfloat162{h2_, h3_}; \
    *(__nv_bfloat162*)(sAl + o_) = __nv_bfloat162{ \
        __float2bfloat16(V.x - __bfloat162float(h0_)), \
        __float2bfloat16(V.y - __bfloat162float(h1_))}; \
    *(__nv_bfloat162*)(sAl + o_ + 2) = __nv_bfloat162{ \
        __float2bfloat16(V.z - __bfloat162float(h2_)), \
        __float2bfloat16(V.w - __bfloat162float(h3_))}; \
} while (0)
#define ST_B(V, U) do { \
    int unit_ = tid + (U) * 256; \
    int r_ = unit_ >> 5, p_ = unit_ & 31; \
    __nv_bfloat16 h0_ = __float2bfloat16(V.x), h1_ = __float2bfloat16(V.y); \
    __nv_bfloat16 h2_ = __float2bfloat16(V.z), h3_ = __float2bfloat16(V.w); \
    int o_ = r_ * SB + p_ * 4; \
    *(__nv_bfloat162*)(sBh + o_)     = __nv_bfloat162{h0_, h1_}; \
    *(__nv_bfloat162*)(sBh + o_ + 2) = __nv_bfloat162{h2_, h3_}; \
    *(__nv_bfloat162*)(sBl + o_) = __nv_bfloat162{ \
        __float2bfloat16(V.x - __bfloat162float(h0_)), \
        __float2bfloat16(V.y - __bfloat162float(h1_))}; \
    *(__nv_bfloat162*)(sBl + o_ + 2) = __nv_bfloat162{ \
        __float2bfloat16(V.z - __bfloat162float(h2_)), \
        __float2bfloat16(V.w - __bfloat162float(h3_))}; \
} while (0)

    constexpr int nch = K / 32;
    PREF(0);

    for (int ch = 0; ch < nch; ch++) {
        // drain prefetched chunk ch into smem (convert fp32 -> bf16 hi/lo)
        ST_A(pa0, 0); ST_A(pa1, 1); ST_A(pa2, 2); ST_A(pa3, 3);
        ST_B(pb0, 0); ST_B(pb1, 1); ST_B(pb2, 2); ST_B(pb3, 3);
        __syncthreads();

        // kick off loads for chunk ch+1; results consumed only next iteration,
        // so their latency hides behind the MMA burst below.
        if (ch + 1 < nch) PREF((ch + 1) * 32);

        #pragma unroll
        for (int kk = 0; kk < 32; kk += 16) {
            const uint32_t aoff = ((wm * 64 + (lane & 15)) * SA + kk + (lane >> 4) * 8) * 2;
            uint4 Ah0, Ah1, Ah2, Ah3, Al0, Al1, Al2, Al3;
            LDM_X4(Ah0.x, Ah0.y, Ah0.z, Ah0.w, sAh0 + aoff);
            LDM_X4(Ah1.x, Ah1.y, Ah1.z, Ah1.w, sAh0 + aoff + 16 * SA * 2);
            LDM_X4(Ah2.x, Ah2.y, Ah2.z, Ah2.w, sAh0 + aoff + 32 * SA * 2);
            LDM_X4(Ah3.x, Ah3.y, Ah3.z, Ah3.w, sAh0 + aoff + 48 * SA * 2);
            LDM_X4(Al0.x, Al0.y, Al0.z, Al0.w, sAl0 + aoff);
            LDM_X4(Al1.x, Al1.y, Al1.z, Al1.w, sAl0 + aoff + 16 * SA * 2);
            LDM_X4(Al2.x, Al2.y, Al2.z, Al2.w, sAl0 + aoff + 32 * SA * 2);
            LDM_X4(Al3.x, Al3.y, Al3.z, Al3.w, sAl0 + aoff + 48 * SA * 2);

            const uint32_t boff = ((kk + (lane & 15)) * SB + wn * 32) * 2;
            uint2 Bh0, Bh1, Bh2, Bh3, Bl0, Bl1, Bl2, Bl3;
            LDM_X2T(Bh0.x, Bh0.y, sBh0 + boff);
            LDM_X2T(Bh1.x, Bh1.y, sBh0 + boff + 16);
            LDM_X2T(Bh2.x, Bh2.y, sBh0 + boff + 32);
            LDM_X2T(Bh3.x, Bh3.y, sBh0 + boff + 48);
            LDM_X2T(Bl0.x, Bl0.y, sBl0 + boff);
            LDM_X2T(Bl1.x, Bl1.y, sBl0 + boff + 16);
            LDM_X2T(Bl2.x, Bl2.y, sBl0 + boff + 32);
            LDM_X2T(Bl3.x, Bl3.y, sBl0 + boff + 48);

            MMA3(c00, Ah0, Al0, Bh0, Bl0); MMA3(c01, Ah0, Al0, Bh1, Bl1);
            MMA3(c02, Ah0, Al0, Bh2, Bl2); MMA3(c03, Ah0, Al0, Bh3, Bl3);
            MMA3(c10, Ah1, Al1, Bh0, Bl0); MMA3(c11, Ah1, Al1, Bh1, Bl1);
            MMA3(c12, Ah1, Al1, Bh2, Bl2); MMA3(c13, Ah1, Al1, Bh3, Bl3);
            MMA3(c20, Ah2, Al2, Bh0, Bl0); MMA3(c21, Ah2, Al2, Bh1, Bl1);
            MMA3(c22, Ah2, Al2, Bh2, Bl2); MMA3(c23, Ah2, Al2, Bh3, Bl3);
            MMA3(c30, Ah3, Al3, Bh0, Bl0); MMA3(c31, Ah3, Al3, Bh1, Bl1);
            MMA3(c32, Ah3, Al3, Bh2, Bl2); MMA3(c33, Ah3, Al3, Bh3, Bl3);
        }
        __syncthreads();
    }
#undef PREF
#undef LDG_A
#undef LDG_B
#undef ST_A
#undef ST_B

    // ---- epilogue ----
    const float* bptr = bias + (size_t)e * Ntot + n0;
#define EPI(C, I, J) do { \
    int r0_ = wm * 64 + (I) * 16 + (lane >> 2); \
    int s0_ = s_slot[r0_], s1_ = s_slot[r0_ + 8]; \
    int col_ = wn * 32 + (J) * 8 + (lane & 3) * 2; \
    float b0_ = bptr[col_], b1_ = bptr[col_ + 1]; \
    if (MODE == 1) { \
        if (s0_ >= 0) { \
            float2 o_ = make_float2(gelu_tanh(C.x + b0_), gelu_tanh(C.y + b1_)); \
            *(float2*)(g_h + (size_t)s0_ * HDIM + n0 + col_) = o_; \
        } \
        if (s1_ >= 0) { \
            float2 o_ = make_float2(gelu_tanh(C.z + b0_), gelu_tanh(C.w + b1_)); \
            *(float2*)(g_h + (size_t)s1_ * HDIM + n0 + col_) = o_; \
        } \
    } else { \
        if (s0_ >= 0) \
            *(float2*)(g_y + (size_t)s0_ * DIN + n0 + col_) = make_float2(C.x + b0_, C.y + b1_); \
        if (s1_ >= 0) \
            *(float2*)(g_y + (size_t)s1_ * DIN + n0 + col_) = make_float2(C.z + b0_, C.w + b1_); \
    } \
} while (0)
    EPI(c00, 0, 0); EPI(c01, 0, 1); EPI(c02, 0, 2); EPI(c03, 0, 3);
    EPI(c10, 1, 0); EPI(c11, 1, 1); EPI(c12, 1, 2); EPI(c13, 1, 3);
    EPI(c20, 2, 0); EPI(c21, 2, 1); EPI(c22, 2, 2); EPI(c23, 2, 3);
    EPI(c30, 3, 0); EPI(c31, 3, 1); EPI(c32, 3, 2); EPI(c33, 3, 3);
#undef EPI
}

// ---------------- combine + loss tail ----------------
__global__ void k_comb(const float* __restrict__ p, float* __restrict__ out) {
    int i = blockIdx.x * blockDim.x + threadIdx.x;
    if (i >= N_TOK * DIN / 4) return;
    int t = i / (DIN / 4);
    int d4 = i % (DIN / 4);
    float p0 = p[t * 2], p1 = p[t * 2 + 1];
    float4 y0 = *(const float4*)(g_y + (size_t)(2 * t) * DIN + d4 * 4);
    float4 y1 = *(const float4*)(g_y + (size_t)(2 * t + 1) * DIN + d4 * 4);
    float4 o;
    o.x = p0 * y0.x + p1 * y1.x;
    o.y = p0 * y0.y + p1 * y1.y;
    o.z = p0 * y0.z + p1 * y1.z;
    o.w = p0 * y0.w + p1 * y1.w;
    *(float4*)(out + (size_t)i * 4) = o;
}
__global__ void k_tail(float* __restrict__ out, int begin, int total) {
    int i = begin + blockIdx.x * blockDim.x + threadIdx.x;
    if (i < total) out[i] = 0.0f;
}

extern "C" void kernel_launch(void* const* d_in, const int* in_sizes, int n_in,
                              void* d_out, int out_size) {
    const float* x    = (const float*)d_in[0];
    const float* prob = (const float*)d_in[1];
    const void*  idx  = d_in[2];
    const float* W1   = (const float*)d_in[3];
    const float* b1   = (const float*)d_in[4];
    const float* W2   = (const float*)d_in[5];
    const float* b2   = (const float*)d_in[6];
    float* out = (float*)d_out;

    k_reset<<<1, 32>>>((const int*)idx);
    k_build<<<NSLOT / 256, 256>>>(idx);

    k_mma<1><<<dim3(HDIM / 128, NSLOT / 128, NEXP), 256>>>(x, W1, b1);
    k_mma<2><<<dim3(DIN / 128, NSLOT / 128, NEXP), 256>>>(nullptr, W2, b2);

    k_comb<<<(N_TOK * DIN / 4 + 255) / 256, 256>>>(prob, out);
    int tail = out_size - N_TOK * DIN;
    if (tail > 0)
        k_tail<<<(tail + 255) / 256, 256>>>(out, N_TOK * DIN, out_size);
    (void)in_sizes; (void)n_in;
}

// round 10
// speedup vs baseline: 2.0659x; 1.0052x over previous
#include <cuda_runtime.h>
#include <cuda_bf16.h>
#include <cstdint>
#include <math.h>

// Problem constants
#define N_TOK 4096
#define DIN   512
#define HDIM  2048
#define NEXP  8
#define NSLOT 8192
#define SA 40    // A smem stride (bf16): 32 + 8 pad
#define SB 136   // B smem stride (bf16): 128 + 8 pad

// dynamic smem stage layout (bytes)
#define AH_OFF 0
#define AL_OFF 10240                // 128*SA*2
#define BH_OFF 20480
#define BL_OFF 29184                // 20480 + 32*SB*2
#define STAGE_BYTES 37888
#define DSMEM (2 * STAGE_BYTES)     // 75776

// ---------------- device scratch (~80 MB, proven-clean footprint) ----------------
__device__ int   g_counts[NEXP];
__device__ int   g_list[NEXP * NSLOT];
__device__ int   g_is64;
__device__ float g_zero[HDIM];                 // stays all-zero
__device__ float g_h[(size_t)NSLOT * HDIM];    // 64 MB hidden (fp32)
__device__ float g_y[(size_t)NSLOT * DIN];     // 16 MB per-slot outputs

// ---------------- PTX macros: scalar operands only ----------------
__device__ __forceinline__ uint32_t smem_u32(const void* p) {
    uint32_t a;
    asm("{ .reg .u64 t; cvta.to.shared.u64 t, %1; cvt.u32.u64 %0, t; }"
        : "=r"(a) : "l"(p));
    return a;
}
#define LDM_X4(r0, r1, r2, r3, a) \
    asm volatile("ldmatrix.sync.aligned.m8n8.x4.shared.b16 {%0,%1,%2,%3}, [%4];" \
                 : "=r"(r0), "=r"(r1), "=r"(r2), "=r"(r3) : "r"(a))
#define LDM_X2T(r0, r1, a) \
    asm volatile("ldmatrix.sync.aligned.m8n8.x2.trans.shared.b16 {%0,%1}, [%2];" \
                 : "=r"(r0), "=r"(r1) : "r"(a))
#define MMA16816(c0, c1, c2, c3, a0, a1, a2, a3, b0, b1) \
    asm volatile("mma.sync.aligned.m16n8k16.row.col.f32.bf16.bf16.f32 " \
                 "{%0,%1,%2,%3}, {%4,%5,%6,%7}, {%8,%9}, {%0,%1,%2,%3};" \
                 : "+f"(c0), "+f"(c1), "+f"(c2), "+f"(c3) \
                 : "r"(a0), "r"(a1), "r"(a2), "r"(a3), "r"(b0), "r"(b1))
// 3-term accumulate: hi*hi + lo*hi + hi*lo
#define MMA3(C, AH, AL, BH, BL) do { \
    MMA16816(C.x, C.y, C.z, C.w, AH.x, AH.y, AH.z, AH.w, BH.x, BH.y); \
    MMA16816(C.x, C.y, C.z, C.w, AL.x, AL.y, AL.z, AL.w, BH.x, BH.y); \
    MMA16816(C.x, C.y, C.z, C.w, AH.x, AH.y, AH.z, AH.w, BL.x, BL.y); \
} while (0)

// ---------------- dispatch ----------------
__global__ void k_reset(const int* idx32) {
    int t = threadIdx.x;
    if (t < NEXP) g_counts[t] = 0;
    if (t == 0) {
        int allz = 1;
        #pragma unroll
        for (int i = 1; i < 32; i += 2)
            if (idx32[i] != 0) allz = 0;
        g_is64 = allz;
    }
}
__global__ void k_build(const void* idxp) {
    int s = blockIdx.x * blockDim.x + threadIdx.x;
    if (s >= NSLOT) return;
    int e = g_is64 ? (int)((const long long*)idxp)[s] : ((const int*)idxp)[s];
    int pos = atomicAdd(&g_counts[e], 1);
    g_list[e * NSLOT + pos] = s;
}

__device__ __forceinline__ float gelu_tanh(float v) {
    float u = 0.7978845608028654f * (v + 0.044715f * v * v * v);
    return 0.5f * v * (1.0f + tanhf(u));
}

// ---------------- fused-convert tensor-core grouped GEMM ----------------
// LDG-prefetch + double-buffered smem: ONE barrier per K-chunk.
// MODE 1: h = gelu(gather(x) @ W1[e] + b1[e])   K=512,  Ntot=2048, A row = slot>>1
// MODE 2: y = gather(h) @ W2[e] + b2[e]         K=2048, Ntot=512,  A row = slot
template <int MODE>
__global__ __launch_bounds__(256, 1)
void k_mma(const float* __restrict__ Asrc_in, const float* __restrict__ W,
           const float* __restrict__ bias) {
    extern __shared__ __align__(16) char dsm[];
    __shared__ const float* s_aptr[128];
    __shared__ int s_slot[128];

    const int e   = blockIdx.z;
    const int cnt = g_counts[e];
    const int m0  = blockIdx.y * 128;
    if (m0 >= cnt) return;
    const int n0  = blockIdx.x * 128;
    const int tid = threadIdx.x;
    const int lane = tid & 31, w = tid >> 5;
    const int wm = w & 1, wn = w >> 1;          // 2x4 warp grid, warp tile 64x32

    constexpr int K    = (MODE == 1) ? DIN : HDIM;
    constexpr int Ntot = (MODE == 1) ? HDIM : DIN;
    const float* Asrc = (MODE == 1) ? Asrc_in : (const float*)g_h;
    const float* Bsrc = W + (size_t)e * K * Ntot;

    if (tid < 128) {
        int m = m0 + tid;
        if (m < cnt) {
            int s = g_list[e * NSLOT + m];
            s_slot[tid] = s;
            int r = (MODE == 1) ? (s >> 1) : s;
            s_aptr[tid] = Asrc + (size_t)r * K;
        } else {
            s_slot[tid] = -1;
            s_aptr[tid] = g_zero;
        }
    }
    __syncthreads();

    const uint32_t dyn0 = smem_u32(dsm);

    float4 c00 = make_float4(0.f, 0.f, 0.f, 0.f), c01 = c00, c02 = c00, c03 = c00;
    float4 c10 = c00, c11 = c00, c12 = c00, c13 = c00;
    float4 c20 = c00, c21 = c00, c22 = c00, c23 = c00;
    float4 c30 = c00, c31 = c00, c32 = c00, c33 = c00;

    // prefetch registers (named scalars)
    float4 pa0, pa1, pa2, pa3, pb0, pb1, pb2, pb3;

#define LDG_A(V, U, K0) do { \
    int unit_ = tid + (U) * 256; \
    int r_ = unit_ >> 3, p_ = unit_ & 7; \
    V = *(const float4*)(s_aptr[r_] + (K0) + p_ * 4); \
} while (0)
#define LDG_B(V, U, K0) do { \
    int unit_ = tid + (U) * 256; \
    int r_ = unit_ >> 5, p_ = unit_ & 31; \
    V = *(const float4*)(Bsrc + (size_t)((K0) + r_) * Ntot + n0 + p_ * 4); \
} while (0)
#define PREF(K0) do { \
    LDG_A(pa0, 0, K0); LDG_A(pa1, 1, K0); LDG_A(pa2, 2, K0); LDG_A(pa3, 3, K0); \
    LDG_B(pb0, 0, K0); LDG_B(pb1, 1, K0); LDG_B(pb2, 2, K0); LDG_B(pb3, 3, K0); \
} while (0)
#define ST_A(V, U, SBASE) do { \
    int unit_ = tid + (U) * 256; \
    int r_ = unit_ >> 3, p_ = unit_ & 7; \
    __nv_bfloat16 h0_ = __float2bfloat16(V.x), h1_ = __float2bfloat16(V.y); \
    __nv_bfloat16 h2_ = __float2bfloat16(V.z), h3_ = __float2bfloat16(V.w); \
    int o_ = (r_ * SA + p_ * 4) * 2; \
    *(__nv_bfloat162*)((SBASE) + AH_OFF + o_)     = __nv_bfloat162{h0_, h1_}; \
    *(__nv_bfloat162*)((SBASE) + AH_OFF + o_ + 4) = __nv_bfloat162{h2_, h3_}; \
    *(__nv_bfloat162*)((SBASE) + AL_OFF + o_) = __nv_bfloat162{ \
        __float2bfloat16(V.x - __bfloat162float(h0_)), \
        __float2bfloat16(V.y - __bfloat162float(h1_))}; \
    *(__nv_bfloat162*)((SBASE) + AL_OFF + o_ + 4) = __nv_bfloat162{ \
        __float2bfloat16(V.z - __bfloat162float(h2_)), \
        __float2bfloat16(V.w - __bfloat162float(h3_))}; \
} while (0)
#define ST_B(V, U, SBASE) do { \
    int unit_ = tid + (U) * 256; \
    int r_ = unit_ >> 5, p_ = unit_ & 31; \
    __nv_bfloat16 h0_ = __float2bfloat16(V.x), h1_ = __float2bfloat16(V.y); \
    __nv_bfloat16 h2_ = __float2bfloat16(V.z), h3_ = __float2bfloat16(V.w); \
    int o_ = (r_ * SB + p_ * 4) * 2; \
    *(__nv_bfloat162*)((SBASE) + BH_OFF + o_)     = __nv_bfloat162{h0_, h1_}; \
    *(__nv_bfloat162*)((SBASE) + BH_OFF + o_ + 4) = __nv_bfloat162{h2_, h3_}; \
    *(__nv_bfloat162*)((SBASE) + BL_OFF + o_) = __nv_bfloat162{ \
        __float2bfloat16(V.x - __bfloat162float(h0_)), \
        __float2bfloat16(V.y - __bfloat162float(h1_))}; \
    *(__nv_bfloat162*)((SBASE) + BL_OFF + o_ + 4) = __nv_bfloat162{ \
        __float2bfloat16(V.z - __bfloat162float(h2_)), \
        __float2bfloat16(V.w - __bfloat162float(h3_))}; \
} while (0)

    constexpr int nch = K / 32;
    PREF(0);

    for (int ch = 0; ch < nch; ch++) {
        char* sb = dsm + (ch & 1) * STAGE_BYTES;
        // drain prefetched chunk ch into smem buffer ch&1 (fp32 -> bf16 hi/lo)
        ST_A(pa0, 0, sb); ST_A(pa1, 1, sb); ST_A(pa2, 2, sb); ST_A(pa3, 3, sb);
        ST_B(pb0, 0, sb); ST_B(pb1, 1, sb); ST_B(pb2, 2, sb); ST_B(pb3, 3, sb);
        __syncthreads();   // ONLY barrier per chunk: stores visible; by barrier-chain
                           // induction all warps finished reading this buffer 2 chunks ago.

        // loads for chunk ch+1 fly behind the MMA burst
        if (ch + 1 < nch) PREF((ch + 1) * 32);

        const uint32_t sAh0 = dyn0 + (ch & 1) * STAGE_BYTES + AH_OFF;
        const uint32_t sAl0 = dyn0 + (ch & 1) * STAGE_BYTES + AL_OFF;
        const uint32_t sBh0 = dyn0 + (ch & 1) * STAGE_BYTES + BH_OFF;
        const uint32_t sBl0 = dyn0 + (ch & 1) * STAGE_BYTES + BL_OFF;

        #pragma unroll
        for (int kk = 0; kk < 32; kk += 16) {
            const uint32_t aoff = ((wm * 64 + (lane & 15)) * SA + kk + (lane >> 4) * 8) * 2;
            uint4 Ah0, Ah1, Ah2, Ah3, Al0, Al1, Al2, Al3;
            LDM_X4(Ah0.x, Ah0.y, Ah0.z, Ah0.w, sAh0 + aoff);
            LDM_X4(Ah1.x, Ah1.y, Ah1.z, Ah1.w, sAh0 + aoff + 16 * SA * 2);
            LDM_X4(Ah2.x, Ah2.y, Ah2.z, Ah2.w, sAh0 + aoff + 32 * SA * 2);
            LDM_X4(Ah3.x, Ah3.y, Ah3.z, Ah3.w, sAh0 + aoff + 48 * SA * 2);
            LDM_X4(Al0.x, Al0.y, Al0.z, Al0.w, sAl0 + aoff);
            LDM_X4(Al1.x, Al1.y, Al1.z, Al1.w, sAl0 + aoff + 16 * SA * 2);
            LDM_X4(Al2.x, Al2.y, Al2.z, Al2.w, sAl0 + aoff + 32 * SA * 2);
            LDM_X4(Al3.x, Al3.y, Al3.z, Al3.w, sAl0 + aoff + 48 * SA * 2);

            const uint32_t boff = ((kk + (lane & 15)) * SB + wn * 32) * 2;
            uint2 Bh0, Bh1, Bh2, Bh3, Bl0, Bl1, Bl2, Bl3;
            LDM_X2T(Bh0.x, Bh0.y, sBh0 + boff);
            LDM_X2T(Bh1.x, Bh1.y, sBh0 + boff + 16);
            LDM_X2T(Bh2.x, Bh2.y, sBh0 + boff + 32);
            LDM_X2T(Bh3.x, Bh3.y, sBh0 + boff + 48);
            LDM_X2T(Bl0.x, Bl0.y, sBl0 + boff);
            LDM_X2T(Bl1.x, Bl1.y, sBl0 + boff + 16);
            LDM_X2T(Bl2.x, Bl2.y, sBl0 + boff + 32);
            LDM_X2T(Bl3.x, Bl3.y, sBl0 + boff + 48);

            MMA3(c00, Ah0, Al0, Bh0, Bl0); MMA3(c01, Ah0, Al0, Bh1, Bl1);
            MMA3(c02, Ah0, Al0, Bh2, Bl2); MMA3(c03, Ah0, Al0, Bh3, Bl3);
            MMA3(c10, Ah1, Al1, Bh0, Bl0); MMA3(c11, Ah1, Al1, Bh1, Bl1);
            MMA3(c12, Ah1, Al1, Bh2, Bl2); MMA3(c13, Ah1, Al1, Bh3, Bl3);
            MMA3(c20, Ah2, Al2, Bh0, Bl0); MMA3(c21, Ah2, Al2, Bh1, Bl1);
            MMA3(c22, Ah2, Al2, Bh2, Bl2); MMA3(c23, Ah2, Al2, Bh3, Bl3);
            MMA3(c30, Ah3, Al3, Bh0, Bl0); MMA3(c31, Ah3, Al3, Bh1, Bl1);
            MMA3(c32, Ah3, Al3, Bh2, Bl2); MMA3(c33, Ah3, Al3, Bh3, Bl3);
        }
        // no trailing barrier: next chunk writes the OTHER buffer.
    }
#undef PREF
#undef LDG_A
#undef LDG_B
#undef ST_A
#undef ST_B

    // ---- epilogue ----
    const float* bptr = bias + (size_t)e * Ntot + n0;
#define EPI(C, I, J) do { \
    int r0_ = wm * 64 + (I) * 16 + (lane >> 2); \
    int s0_ = s_slot[r0_], s1_ = s_slot[r0_ + 8]; \
    int col_ = wn * 32 + (J) * 8 + (lane & 3) * 2; \
    float b0_ = bptr[col_], b1_ = bptr[col_ + 1]; \
    if (MODE == 1) { \
        if (s0_ >= 0) { \
            float2 o_ = make_float2(gelu_tanh(C.x + b0_), gelu_tanh(C.y + b1_)); \
            *(float2*)(g_h + (size_t)s0_ * HDIM + n0 + col_) = o_; \
        } \
        if (s1_ >= 0) { \
            float2 o_ = make_float2(gelu_tanh(C.z + b0_), gelu_tanh(C.w + b1_)); \
            *(float2*)(g_h + (size_t)s1_ * HDIM + n0 + col_) = o_; \
        } \
    } else { \
        if (s0_ >= 0) \
            *(float2*)(g_y + (size_t)s0_ * DIN + n0 + col_) = make_float2(C.x + b0_, C.y + b1_); \
        if (s1_ >= 0) \
            *(float2*)(g_y + (size_t)s1_ * DIN + n0 + col_) = make_float2(C.z + b0_, C.w + b1_); \
    } \
} while (0)
    EPI(c00, 0, 0); EPI(c01, 0, 1); EPI(c02, 0, 2); EPI(c03, 0, 3);
    EPI(c10, 1, 0); EPI(c11, 1, 1); EPI(c12, 1, 2); EPI(c13, 1, 3);
    EPI(c20, 2, 0); EPI(c21, 2, 1); EPI(c22, 2, 2); EPI(c23, 2, 3);
    EPI(c30, 3, 0); EPI(c31, 3, 1); EPI(c32, 3, 2); EPI(c33, 3, 3);
#undef EPI
}

// ---------------- combine + loss tail ----------------
__global__ void k_comb(const float* __restrict__ p, float* __restrict__ out) {
    int i = blockIdx.x * blockDim.x + threadIdx.x;
    if (i >= N_TOK * DIN / 4) return;
    int t = i / (DIN / 4);
    int d4 = i % (DIN / 4);
    float p0 = p[t * 2], p1 = p[t * 2 + 1];
    float4 y0 = *(const float4*)(g_y + (size_t)(2 * t) * DIN + d4 * 4);
    float4 y1 = *(const float4*)(g_y + (size_t)(2 * t + 1) * DIN + d4 * 4);
    float4 o;
    o.x = p0 * y0.x + p1 * y1.x;
    o.y = p0 * y0.y + p1 * y1.y;
    o.z = p0 * y0.z + p1 * y1.z;
    o.w = p0 * y0.w + p1 * y1.w;
    *(float4*)(out + (size_t)i * 4) = o;
}
__global__ void k_tail(float* __restrict__ out, int begin, int total) {
    int i = begin + blockIdx.x * blockDim.x + threadIdx.x;
    if (i < total) out[i] = 0.0f;
}

extern "C" void kernel_launch(void* const* d_in, const int* in_sizes, int n_in,
                              void* d_out, int out_size) {
    const float* x    = (const float*)d_in[0];
    const float* prob = (const float*)d_in[1];
    const void*  idx  = d_in[2];
    const float* W1   = (const float*)d_in[3];
    const float* b1   = (const float*)d_in[4];
    const float* W2   = (const float*)d_in[5];
    const float* b2   = (const float*)d_in[6];
    float* out = (float*)d_out;

    static int attr_done = 0;
    if (!attr_done) {
        cudaFuncSetAttribute(k_mma<1>, cudaFuncAttributeMaxDynamicSharedMemorySize, DSMEM);
        cudaFuncSetAttribute(k_mma<2>, cudaFuncAttributeMaxDynamicSharedMemorySize, DSMEM);
        attr_done = 1;
    }

    k_reset<<<1, 32>>>((const int*)idx);
    k_build<<<NSLOT / 256, 256>>>(idx);

    k_mma<1><<<dim3(HDIM / 128, NSLOT / 128, NEXP), 256, DSMEM>>>(x, W1, b1);
    k_mma<2><<<dim3(DIN / 128, NSLOT / 128, NEXP), 256, DSMEM>>>(nullptr, W2, b2);

    k_comb<<<(N_TOK * DIN / 4 + 255) / 256, 256>>>(prob, out);
    int tail = out_size - N_TOK * DIN;
    if (tail > 0)
        k_tail<<<(tail + 255) / 256, 256>>>(out, N_TOK * DIN, out_size);
    (void)in_sizes; (void)n_in;
}